// round 13
// baseline (speedup 1.0000x reference)
#include <cuda_runtime.h>
#include <cuda_fp16.h>
#include <cstdint>

#define B_    8
#define S_    2048
#define NEXP  16
#define DIN_  1024
#define DOUT_ 1024

// ---------------- scratch ----------------
__device__ __align__(1024) __half g_Xhi[B_ * S_ * DIN_];
__device__ __align__(1024) __half g_Whi[B_ * DOUT_ * DIN_];
__device__ float g_mb[B_ * DOUT_];

// ---------------- PTX helpers (target-generic, sm_80+) ----------------
__device__ __forceinline__ uint32_t smem_u32(const void* p) {
    uint32_t a;
    asm("{ .reg .u64 t; cvta.to.shared.u64 t, %1; cvt.u32.u64 %0, t; }" : "=r"(a) : "l"(p));
    return a;
}
__device__ __forceinline__ void cpa16(uint32_t s, const void* g) {
    asm volatile("cp.async.cg.shared.global.L2::256B [%0], [%1], 16;" :: "r"(s), "l"(g));
}
__device__ __forceinline__ void cpa_commit() { asm volatile("cp.async.commit_group;" ::: "memory"); }
__device__ __forceinline__ void cpa_wait1()  { asm volatile("cp.async.wait_group 1;" ::: "memory"); }
__device__ __forceinline__ void cpa_wait0()  { asm volatile("cp.async.wait_group 0;" ::: "memory"); }

__device__ __forceinline__ void ldsm_x4(uint32_t (&r)[4], uint32_t addr) {
    asm volatile("ldmatrix.sync.aligned.m8n8.x4.shared.b16 {%0,%1,%2,%3}, [%4];"
                 : "=r"(r[0]), "=r"(r[1]), "=r"(r[2]), "=r"(r[3]) : "r"(addr));
}
__device__ __forceinline__ void mma16816(float (&d)[4], const uint32_t (&a)[4],
                                         uint32_t b0, uint32_t b1) {
    asm volatile(
        "mma.sync.aligned.m16n8k16.row.col.f32.f16.f16.f32 "
        "{%0,%1,%2,%3}, {%4,%5,%6,%7}, {%8,%9}, {%0,%1,%2,%3};"
        : "+f"(d[0]), "+f"(d[1]), "+f"(d[2]), "+f"(d[3])
        : "r"(a[0]), "r"(a[1]), "r"(a[2]), "r"(a[3]), "r"(b0), "r"(b1));
}

static __device__ __forceinline__ uint32_t swz(uint32_t off) {
    return off ^ ((off >> 3) & 0x70);
}

// ---------------- merged prep kernel (R8 version — measured ~28.7us) ----------------
#define NMIXW (DOUT_ * DIN_ / 4 / 256)           // 1024
#define NMIXB (B_ * DOUT_ / 256)                 // 32
#define NCONV (B_ * S_ * DIN_ / 4 / 1024)        // 4096

__global__ void prep_kernel(const float* __restrict__ X, const float* __restrict__ p,
                            const float* __restrict__ W, const float* __restrict__ bias) {
    const int bid = blockIdx.x;
    if (bid < NMIXW) {
        __shared__ float sp[B_ * NEXP];
        if (threadIdx.x < B_ * NEXP) sp[threadIdx.x] = p[threadIdx.x];
        __syncthreads();

        int idx = bid * 256 + threadIdx.x;
        const int stride4 = DOUT_ * DIN_ / 4;
        const float4* W4 = reinterpret_cast<const float4*>(W);
        float4 acc[B_];
#pragma unroll
        for (int b = 0; b < B_; b++) acc[b] = make_float4(0.f, 0.f, 0.f, 0.f);
#pragma unroll
        for (int n = 0; n < NEXP; n++) {
            float4 w = W4[n * stride4 + idx];
#pragma unroll
            for (int b = 0; b < B_; b++) {
                float s = sp[b * NEXP + n];
                acc[b].x += s * w.x; acc[b].y += s * w.y;
                acc[b].z += s * w.z; acc[b].w += s * w.w;
            }
        }
#pragma unroll
        for (int b = 0; b < B_; b++) {
            union { __half h[4]; uint2 u; } hi;
            hi.h[0] = __float2half_rn(acc[b].x);
            hi.h[1] = __float2half_rn(acc[b].y);
            hi.h[2] = __float2half_rn(acc[b].z);
            hi.h[3] = __float2half_rn(acc[b].w);
            reinterpret_cast<uint2*>(g_Whi)[b * stride4 + idx] = hi.u;
        }
    } else if (bid < NMIXW + NMIXB) {
        int idx = (bid - NMIXW) * 256 + threadIdx.x;
        int b = idx >> 10;
        int i = idx & 1023;
        float s = 0.f;
#pragma unroll
        for (int n = 0; n < NEXP; n++) s += p[b * NEXP + n] * bias[n * DOUT_ + i];
        g_mb[idx] = s;
    } else {
        int base = (bid - NMIXW - NMIXB) * 1024 + threadIdx.x;
        float4 v[4];
#pragma unroll
        for (int j = 0; j < 4; j++) v[j] = reinterpret_cast<const float4*>(X)[base + 256 * j];
#pragma unroll
        for (int j = 0; j < 4; j++) {
            union { __half h[4]; uint2 u; } hi;
            hi.h[0] = __float2half_rn(v[j].x);
            hi.h[1] = __float2half_rn(v[j].y);
            hi.h[2] = __float2half_rn(v[j].z);
            hi.h[3] = __float2half_rn(v[j].w);
            reinterpret_cast<uint2*>(g_Xhi)[base + 256 * j] = hi.u;
        }
    }
}

// ---------------- persistent mma.sync GEMM: BM=64, BN=128, 128 thr, 4 CTAs/SM ----------------
#define BM 64
#define BN 128
#define BKT 64
#define NT (DIN_ / BKT)       // 16
#define NTILES 2048           // (S_/BM) * (DOUT_/BN) * B_
#define GRID_P 592            // 4 * 148 SMs

#define STAGE_BYTES 24576     // A 8KB + W 16KB
#define OFF_A 0
#define OFF_W 8192
#define SMEM_TOTAL (2 * STAGE_BYTES + 512)   // 49664

__device__ __forceinline__ void load_kt(uint32_t stage_base, int b, int m0, int n0,
                                        int kt, int tid) {
    const __half* xa = g_Xhi + ((size_t)b * S_ + m0) * DIN_ + kt * BKT;
    const __half* wb = g_Whi + ((size_t)b * DOUT_ + n0) * DIN_ + kt * BKT;

#pragma unroll
    for (int i = 0; i < 4; i++) {
        int c = tid + 128 * i;
        int row = c >> 3, c16 = c & 7;
        uint32_t so = swz(row * 128 + c16 * 16);
        cpa16(stage_base + OFF_A + so, xa + (size_t)row * DIN_ + c16 * 8);
    }
#pragma unroll
    for (int i = 0; i < 8; i++) {
        int c = tid + 128 * i;
        int row = c >> 3, c16 = c & 7;
        uint32_t so = swz(row * 128 + c16 * 16);
        cpa16(stage_base + OFF_W + so, wb + (size_t)row * DIN_ + c16 * 8);
    }
    cpa_commit();
}

__global__ __launch_bounds__(128, 4) void gemm_kernel(float* __restrict__ Out) {
    extern __shared__ char smem[];
    const uint32_t sb = smem_u32(smem);
    const int tid = threadIdx.x;
    const int wid = tid >> 5;
    const int lane = tid & 31;

    const int wm = (wid >> 1) * 32;   // 2 warps in m
    const int wn = (wid & 1) * 64;    // 2 warps in n

    const int a_row  = lane & 15;
    const int a_col8 = (lane >> 4) * 8;
    const int b_nhalf = lane >> 4;
    const int b_khalf = (lane >> 3) & 1;
    const int b_row   = lane & 7;

    for (int tile = blockIdx.x; tile < NTILES; tile += GRID_P) {
        // x-fastest mapping: consecutive tiles share the A (X) tile
        const int n0 = (tile & 7) * BN;
        const int m0 = ((tile >> 3) & 31) * BM;
        const int b  = tile >> 8;

        float acc[2][8][4];
#pragma unroll
        for (int mi = 0; mi < 2; mi++)
#pragma unroll
            for (int nb = 0; nb < 8; nb++)
#pragma unroll
                for (int j = 0; j < 4; j++) acc[mi][nb][j] = 0.f;

        load_kt(sb, b, m0, n0, 0, tid);
        load_kt(sb + STAGE_BYTES, b, m0, n0, 1, tid);

#pragma unroll 2
        for (int kt = 0; kt < NT; kt++) {
            const uint32_t stage = sb + (uint32_t)(kt & 1) * STAGE_BYTES;

            if (kt < NT - 1) cpa_wait1(); else cpa_wait0();
            __syncthreads();

#pragma unroll
            for (int ks = 0; ks < 4; ks++) {
                const int k0 = ks * 16;

                uint32_t af[2][4], wf[4][4];

#pragma unroll
                for (int mi = 0; mi < 2; mi++) {
                    uint32_t off = swz((uint32_t)(wm + mi * 16 + a_row) * 128 +
                                       (uint32_t)(k0 + a_col8) * 2);
                    ldsm_x4(af[mi], stage + OFF_A + off);
                }
#pragma unroll
                for (int p = 0; p < 4; p++) {
                    int nrow = wn + (p * 2 + b_nhalf) * 8 + b_row;
                    uint32_t off = swz((uint32_t)nrow * 128 +
                                       (uint32_t)(k0 + b_khalf * 8) * 2);
                    ldsm_x4(wf[p], stage + OFF_W + off);
                }

#pragma unroll
                for (int mi = 0; mi < 2; mi++)
#pragma unroll
                    for (int nb = 0; nb < 8; nb++)
                        mma16816(acc[mi][nb], af[mi], wf[nb >> 1][(nb & 1) * 2],
                                 wf[nb >> 1][(nb & 1) * 2 + 1]);
            }

            __syncthreads();
            if (kt + 2 < NT) {
                load_kt(stage, b, m0, n0, kt + 2, tid);
            }
        }

        // epilogue: bias direct from global (L2-resident)
        const float* mb = g_mb + b * DOUT_ + n0;
        const int c_row = lane >> 2;
        const int c_col = 2 * (lane & 3);
#pragma unroll
        for (int mi = 0; mi < 2; mi++) {
            int row0 = m0 + wm + mi * 16 + c_row;
            float* o0 = Out + ((size_t)b * S_ + row0) * DOUT_ + n0;
            float* o1 = o0 + 8 * DOUT_;
#pragma unroll
            for (int nb = 0; nb < 8; nb++) {
                int col = wn + nb * 8 + c_col;
                float bx = __ldg(mb + col), by = __ldg(mb + col + 1);
                float2 v0 = make_float2(acc[mi][nb][0] + bx, acc[mi][nb][1] + by);
                float2 v1 = make_float2(acc[mi][nb][2] + bx, acc[mi][nb][3] + by);
                *reinterpret_cast<float2*>(o0 + col) = v0;
                *reinterpret_cast<float2*>(o1 + col) = v1;
            }
        }
        __syncthreads();   // all warps done with smem before next tile's loads
    }
}

// ---------------- launch ----------------
extern "C" void kernel_launch(void* const* d_in, const int* in_sizes, int n_in,
                              void* d_out, int out_size) {
    const float* x    = (const float*)d_in[0];   // [B, S, DIN]
    const float* p    = (const float*)d_in[1];   // [B, N]
    const float* W    = (const float*)d_in[2];   // [N, DOUT, DIN]
    const float* bias = (const float*)d_in[3];   // [N, DOUT]
    float* out = (float*)d_out;                  // [B, S, DOUT]

    cudaFuncSetAttribute(gemm_kernel, cudaFuncAttributeMaxDynamicSharedMemorySize,
                         SMEM_TOTAL);

    prep_kernel<<<NMIXW + NMIXB + NCONV, 256>>>(x, p, W, bias);

    gemm_kernel<<<GRID_P, 128, SMEM_TOTAL>>>(out);
}

// round 14
// speedup vs baseline: 1.1450x; 1.1450x over previous
#include <cuda_runtime.h>
#include <cuda_fp16.h>
#include <cstdint>

#define B_    8
#define S_    2048
#define NEXP  16
#define DIN_  1024
#define DOUT_ 1024

// ---------------- scratch ----------------
__device__ __align__(1024) __half g_Xhi[B_ * S_ * DIN_];
__device__ __align__(1024) __half g_Whi[B_ * DOUT_ * DIN_];
__device__ float g_mb[B_ * DOUT_];

// ---------------- PTX helpers (target-generic, sm_80+) ----------------
__device__ __forceinline__ uint32_t smem_u32(const void* p) {
    uint32_t a;
    asm("{ .reg .u64 t; cvta.to.shared.u64 t, %1; cvt.u32.u64 %0, t; }" : "=r"(a) : "l"(p));
    return a;
}
__device__ __forceinline__ void cpa16(uint32_t s, const void* g) {
    asm volatile("cp.async.cg.shared.global.L2::256B [%0], [%1], 16;" :: "r"(s), "l"(g));
}
__device__ __forceinline__ void cpa_commit() { asm volatile("cp.async.commit_group;" ::: "memory"); }
__device__ __forceinline__ void cpa_wait1()  { asm volatile("cp.async.wait_group 1;" ::: "memory"); }
__device__ __forceinline__ void cpa_wait0()  { asm volatile("cp.async.wait_group 0;" ::: "memory"); }

__device__ __forceinline__ void ldsm_x4(uint32_t (&r)[4], uint32_t addr) {
    asm volatile("ldmatrix.sync.aligned.m8n8.x4.shared.b16 {%0,%1,%2,%3}, [%4];"
                 : "=r"(r[0]), "=r"(r[1]), "=r"(r[2]), "=r"(r[3]) : "r"(addr));
}
__device__ __forceinline__ void mma16816(float (&d)[4], const uint32_t (&a)[4],
                                         uint32_t b0, uint32_t b1) {
    asm volatile(
        "mma.sync.aligned.m16n8k16.row.col.f32.f16.f16.f32 "
        "{%0,%1,%2,%3}, {%4,%5,%6,%7}, {%8,%9}, {%0,%1,%2,%3};"
        : "+f"(d[0]), "+f"(d[1]), "+f"(d[2]), "+f"(d[3])
        : "r"(a[0]), "r"(a[1]), "r"(a[2]), "r"(a[3]), "r"(b0), "r"(b1));
}

static __device__ __forceinline__ uint32_t swz(uint32_t off) {
    return off ^ ((off >> 3) & 0x70);
}

// streaming fp32x4 load (evict-first: data read exactly once)
__device__ __forceinline__ float4 ldcs4(const float4* p) { return __ldcs(p); }

// ---------------- merged prep kernel (R8 structure + streaming reads) ----------------
#define NMIXW (DOUT_ * DIN_ / 4 / 256)           // 1024
#define NMIXB (B_ * DOUT_ / 256)                 // 32
#define NCONV (B_ * S_ * DIN_ / 4 / 1024)        // 4096

__global__ void prep_kernel(const float* __restrict__ X, const float* __restrict__ p,
                            const float* __restrict__ W, const float* __restrict__ bias) {
    const int bid = blockIdx.x;
    if (bid < NMIXW) {
        __shared__ float sp[B_ * NEXP];
        if (threadIdx.x < B_ * NEXP) sp[threadIdx.x] = p[threadIdx.x];
        __syncthreads();

        int idx = bid * 256 + threadIdx.x;
        const int stride4 = DOUT_ * DIN_ / 4;
        const float4* W4 = reinterpret_cast<const float4*>(W);
        float4 acc[B_];
#pragma unroll
        for (int b = 0; b < B_; b++) acc[b] = make_float4(0.f, 0.f, 0.f, 0.f);
#pragma unroll
        for (int n = 0; n < NEXP; n++) {
            float4 w = ldcs4(W4 + n * stride4 + idx);   // W read once: evict-first
#pragma unroll
            for (int b = 0; b < B_; b++) {
                float s = sp[b * NEXP + n];
                acc[b].x += s * w.x; acc[b].y += s * w.y;
                acc[b].z += s * w.z; acc[b].w += s * w.w;
            }
        }
#pragma unroll
        for (int b = 0; b < B_; b++) {
            union { __half h[4]; uint2 u; } hi;
            hi.h[0] = __float2half_rn(acc[b].x);
            hi.h[1] = __float2half_rn(acc[b].y);
            hi.h[2] = __float2half_rn(acc[b].z);
            hi.h[3] = __float2half_rn(acc[b].w);
            reinterpret_cast<uint2*>(g_Whi)[b * stride4 + idx] = hi.u;
        }
    } else if (bid < NMIXW + NMIXB) {
        int idx = (bid - NMIXW) * 256 + threadIdx.x;
        int b = idx >> 10;
        int i = idx & 1023;
        float s = 0.f;
#pragma unroll
        for (int n = 0; n < NEXP; n++) s += p[b * NEXP + n] * bias[n * DOUT_ + i];
        g_mb[idx] = s;
    } else {
        int base = (bid - NMIXW - NMIXB) * 1024 + threadIdx.x;
        float4 v[4];
#pragma unroll
        for (int j = 0; j < 4; j++)
            v[j] = ldcs4(reinterpret_cast<const float4*>(X) + base + 256 * j);  // X read once
#pragma unroll
        for (int j = 0; j < 4; j++) {
            union { __half h[4]; uint2 u; } hi;
            hi.h[0] = __float2half_rn(v[j].x);
            hi.h[1] = __float2half_rn(v[j].y);
            hi.h[2] = __float2half_rn(v[j].z);
            hi.h[3] = __float2half_rn(v[j].w);
            reinterpret_cast<uint2*>(g_Xhi)[base + 256 * j] = hi.u;
        }
    }
}

// ---------------- mma.sync GEMM: R11 verbatim (measured 83.5us twice) ----------------
#define BM 64
#define BN 128
#define BKT 64
#define NT (DIN_ / BKT)       // 16

#define STAGE_BYTES 24576     // A 8KB + W 16KB
#define OFF_A 0
#define OFF_W 8192
#define SM_BIAS (2 * STAGE_BYTES)
#define SMEM_TOTAL (2 * STAGE_BYTES + 512)   // 49664

__device__ __forceinline__ void load_kt(uint32_t stage_base, int b, int m0, int n0,
                                        int kt, int tid) {
    const __half* xa = g_Xhi + ((size_t)b * S_ + m0) * DIN_ + kt * BKT;
    const __half* wb = g_Whi + ((size_t)b * DOUT_ + n0) * DIN_ + kt * BKT;

#pragma unroll
    for (int i = 0; i < 4; i++) {
        int c = tid + 128 * i;
        int row = c >> 3, c16 = c & 7;
        uint32_t so = swz(row * 128 + c16 * 16);
        cpa16(stage_base + OFF_A + so, xa + (size_t)row * DIN_ + c16 * 8);
    }
#pragma unroll
    for (int i = 0; i < 8; i++) {
        int c = tid + 128 * i;
        int row = c >> 3, c16 = c & 7;
        uint32_t so = swz(row * 128 + c16 * 16);
        cpa16(stage_base + OFF_W + so, wb + (size_t)row * DIN_ + c16 * 8);
    }
    cpa_commit();
}

__global__ __launch_bounds__(128, 4) void gemm_kernel(float* __restrict__ Out) {
    extern __shared__ char smem[];
    const uint32_t sb = smem_u32(smem);
    const int tid = threadIdx.x;
    const int wid = tid >> 5;
    const int lane = tid & 31;

    const int b  = blockIdx.z;
    const int m0 = blockIdx.y * BM;
    const int n0 = blockIdx.x * BN;

    const int wm = (wid >> 1) * 32;   // 2 warps in m
    const int wn = (wid & 1) * 64;    // 2 warps in n

    reinterpret_cast<float*>(smem + SM_BIAS)[tid] = g_mb[b * DOUT_ + n0 + tid];

    float acc[2][8][4];
#pragma unroll
    for (int mi = 0; mi < 2; mi++)
#pragma unroll
        for (int nb = 0; nb < 8; nb++)
#pragma unroll
            for (int j = 0; j < 4; j++) acc[mi][nb][j] = 0.f;

    load_kt(sb, b, m0, n0, 0, tid);
    load_kt(sb + STAGE_BYTES, b, m0, n0, 1, tid);

    const int a_row  = lane & 15;
    const int a_col8 = (lane >> 4) * 8;
    const int b_nhalf = lane >> 4;
    const int b_khalf = (lane >> 3) & 1;
    const int b_row   = lane & 7;

#pragma unroll 2
    for (int kt = 0; kt < NT; kt++) {
        const uint32_t stage = sb + (uint32_t)(kt & 1) * STAGE_BYTES;

        if (kt < NT - 1) cpa_wait1(); else cpa_wait0();
        __syncthreads();

#pragma unroll
        for (int ks = 0; ks < 4; ks++) {
            const int k0 = ks * 16;

            uint32_t af[2][4], wf[4][4];

#pragma unroll
            for (int mi = 0; mi < 2; mi++) {
                uint32_t off = swz((uint32_t)(wm + mi * 16 + a_row) * 128 +
                                   (uint32_t)(k0 + a_col8) * 2);
                ldsm_x4(af[mi], stage + OFF_A + off);
            }
#pragma unroll
            for (int p = 0; p < 4; p++) {
                int nrow = wn + (p * 2 + b_nhalf) * 8 + b_row;
                uint32_t off = swz((uint32_t)nrow * 128 +
                                   (uint32_t)(k0 + b_khalf * 8) * 2);
                ldsm_x4(wf[p], stage + OFF_W + off);
            }

#pragma unroll
            for (int mi = 0; mi < 2; mi++)
#pragma unroll
                for (int nb = 0; nb < 8; nb++)
                    mma16816(acc[mi][nb], af[mi], wf[nb >> 1][(nb & 1) * 2],
                             wf[nb >> 1][(nb & 1) * 2 + 1]);
        }

        __syncthreads();
        if (kt + 2 < NT) {
            load_kt(stage, b, m0, n0, kt + 2, tid);
        }
    }

    const float* sBias = reinterpret_cast<const float*>(smem + SM_BIAS);
    const int c_row = lane >> 2;
    const int c_col = 2 * (lane & 3);
#pragma unroll
    for (int mi = 0; mi < 2; mi++) {
        int row0 = m0 + wm + mi * 16 + c_row;
        float* o0 = Out + ((size_t)b * S_ + row0) * DOUT_ + n0;
        float* o1 = o0 + 8 * DOUT_;
#pragma unroll
        for (int nb = 0; nb < 8; nb++) {
            int col = wn + nb * 8 + c_col;
            float bx = sBias[col], by = sBias[col + 1];
            float2 v0 = make_float2(acc[mi][nb][0] + bx, acc[mi][nb][1] + by);
            float2 v1 = make_float2(acc[mi][nb][2] + bx, acc[mi][nb][3] + by);
            *reinterpret_cast<float2*>(o0 + col) = v0;
            *reinterpret_cast<float2*>(o1 + col) = v1;
        }
    }
}

// ---------------- launch ----------------
extern "C" void kernel_launch(void* const* d_in, const int* in_sizes, int n_in,
                              void* d_out, int out_size) {
    const float* x    = (const float*)d_in[0];   // [B, S, DIN]
    const float* p    = (const float*)d_in[1];   // [B, N]
    const float* W    = (const float*)d_in[2];   // [N, DOUT, DIN]
    const float* bias = (const float*)d_in[3];   // [N, DOUT]
    float* out = (float*)d_out;                  // [B, S, DOUT]

    cudaFuncSetAttribute(gemm_kernel, cudaFuncAttributeMaxDynamicSharedMemorySize,
                         SMEM_TOTAL);

    prep_kernel<<<NMIXW + NMIXB + NCONV, 256>>>(x, p, W, bias);

    dim3 grid(DOUT_ / BN, S_ / BM, B_);          // (8, 32, 8) = 2048 CTAs
    gemm_kernel<<<grid, 128, SMEM_TOTAL>>>(out);
}